// round 15
// baseline (speedup 1.0000x reference)
#include <cuda_runtime.h>
#include <cuda_fp16.h>
#include <cstdint>

// ImageLinearAttention via warp-level mma.sync (m16n8k16 f16->f32), ldmatrix
// fragment loads, 512-thread CTAs, cp.async weight feed.
// B=4, C=128, n=16384, HEADS=8, KD=VD=64.
//
// P0: convert Wk/Wv/Wq to fp16 once.
// P1: per (b,tile), per chunk p: phase1 = FUSED K+V proj (x fragments shared,
//     6 ldmatrix : 16 mma per k-step) -> ekT/vT; phase2 = ctx partials +
//     q-proj (warp = 16 tok x 1 head) -> shfl softmax -> qn to gmem.
// P2: 256 CTAs (bh x 8 d-slices): reduce ctx 128->1, rS, fold Wo -> M (fp16).
// P3: pure GEMM out = M*qn^T + bo, K=512, cp.async 3-deep pipelined tiles.

#define ROWB 136                      // halves per smem row (128 + 8 pad)
#define QSCALE 0.35355339059327373f   // 64^-0.25

__device__ float  g_ctxp[(size_t)512 * 8 * 64 * 64];            // [bt][head][d][e]
__device__ float  g_spart[512 * 512];                            // [dim512][bt]
__device__ __align__(128) __half g_qs[(size_t)512 * 4 * 16384];  // [bt][p][tok][dim]
__device__ __align__(128) __half g_Mh[4 * 4 * 16384];            // [b][p][o][hd128]
__device__ __align__(128) __half g_W16[3 * 512 * 128];           // [kvq][dim][ch] fp16

extern __shared__ char smraw[];

// ---------------- PTX helpers ----------------
__device__ __forceinline__ uint32_t smem_u32(const void* p) {
    uint32_t a;
    asm("{ .reg .u64 t; cvta.to.shared.u64 t, %1; cvt.u32.u64 %0, t; }" : "=r"(a) : "l"(p));
    return a;
}
__device__ __forceinline__ void mma16816(float c[4], const uint32_t a[4],
                                         const uint32_t b[2]) {
    asm volatile(
        "mma.sync.aligned.m16n8k16.row.col.f32.f16.f16.f32 "
        "{%0,%1,%2,%3}, {%4,%5,%6,%7}, {%8,%9}, {%0,%1,%2,%3};"
        : "+f"(c[0]), "+f"(c[1]), "+f"(c[2]), "+f"(c[3])
        : "r"(a[0]), "r"(a[1]), "r"(a[2]), "r"(a[3]), "r"(b[0]), "r"(b[1]));
}
__device__ __forceinline__ void ldmx4(uint32_t r[4], uint32_t addr) {
    asm volatile("ldmatrix.sync.aligned.m8n8.x4.shared.b16 {%0,%1,%2,%3}, [%4];"
        : "=r"(r[0]), "=r"(r[1]), "=r"(r[2]), "=r"(r[3]) : "r"(addr));
}
#define CP16(dst, src) asm volatile("cp.async.cg.shared.global [%0], [%1], 16;" :: "r"(dst), "l"(src))
#define CPCOMMIT()     asm volatile("cp.async.commit_group;" ::: "memory")
#define CPWAIT(n)      asm volatile("cp.async.wait_group %0;" :: "n"(n) : "memory")

__device__ __forceinline__ uint32_t a_addr(uint32_t base, int r0, int k0) {
    const int l = threadIdx.x & 31;
    return base + ((r0 + (l & 15)) * ROWB + k0 + ((l >> 4) << 3)) * 2;
}
__device__ __forceinline__ uint32_t b_addr(uint32_t base, int n0, int k0) {
    const int l = threadIdx.x & 31;
    return base + ((n0 + (l & 7) + ((l >> 4) << 3)) * ROWB + k0 + (((l >> 3) & 1) << 3)) * 2;
}
// 32x32 warp-tile GEMM over K=128, fragment double-buffered.
__device__ __forceinline__ void gemm32x32(float C[2][4][4], uint32_t A, uint32_t B,
                                          int wm, int wn) {
    uint32_t a0[2][4], a1[2][4], b0[2][4], b1[2][4];
    ldmx4(a0[0], a_addr(A, wm, 0));
    ldmx4(a1[0], a_addr(A, wm + 16, 0));
    ldmx4(b0[0], b_addr(B, wn, 0));
    ldmx4(b1[0], b_addr(B, wn + 16, 0));
    #pragma unroll
    for (int s = 0; s < 8; s++) {
        const int cur = s & 1, nxt = cur ^ 1;
        if (s < 7) {
            const int k1 = (s + 1) << 4;
            ldmx4(a0[nxt], a_addr(A, wm, k1));
            ldmx4(a1[nxt], a_addr(A, wm + 16, k1));
            ldmx4(b0[nxt], b_addr(B, wn, k1));
            ldmx4(b1[nxt], b_addr(B, wn + 16, k1));
        }
        mma16816(C[0][0], a0[cur], b0[cur] + 0);  mma16816(C[0][1], a0[cur], b0[cur] + 2);
        mma16816(C[0][2], a0[cur], b1[cur] + 0);  mma16816(C[0][3], a0[cur], b1[cur] + 2);
        mma16816(C[1][0], a1[cur], b0[cur] + 0);  mma16816(C[1][1], a1[cur], b0[cur] + 2);
        mma16816(C[1][2], a1[cur], b1[cur] + 0);  mma16816(C[1][3], a1[cur], b1[cur] + 2);
    }
}
// Fused K+V projection: shared x fragments, 6 ldmatrix : 16 mma per k-step.
__device__ __forceinline__ void gemmKV(float CK[2][4][4], float CV[2][4][4],
                                       uint32_t WK, uint32_t WV, uint32_t X,
                                       int wm, int wn) {
    #pragma unroll
    for (int k0 = 0; k0 < 128; k0 += 16) {
        uint32_t bx0[4], bx1[4], ak0[4], ak1[4], av0[4], av1[4];
        ldmx4(bx0, b_addr(X, wn, k0));
        ldmx4(bx1, b_addr(X, wn + 16, k0));
        ldmx4(ak0, a_addr(WK, wm, k0));
        ldmx4(ak1, a_addr(WK, wm + 16, k0));
        ldmx4(av0, a_addr(WV, wm, k0));
        ldmx4(av1, a_addr(WV, wm + 16, k0));
        mma16816(CK[0][0], ak0, bx0 + 0);  mma16816(CK[0][1], ak0, bx0 + 2);
        mma16816(CK[0][2], ak0, bx1 + 0);  mma16816(CK[0][3], ak0, bx1 + 2);
        mma16816(CK[1][0], ak1, bx0 + 0);  mma16816(CK[1][1], ak1, bx0 + 2);
        mma16816(CK[1][2], ak1, bx1 + 0);  mma16816(CK[1][3], ak1, bx1 + 2);
        mma16816(CV[0][0], av0, bx0 + 0);  mma16816(CV[0][1], av0, bx0 + 2);
        mma16816(CV[0][2], av0, bx1 + 0);  mma16816(CV[0][3], av0, bx1 + 2);
        mma16816(CV[1][0], av1, bx0 + 0);  mma16816(CV[1][1], av1, bx0 + 2);
        mma16816(CV[1][2], av1, bx1 + 0);  mma16816(CV[1][3], av1, bx1 + 2);
    }
}
__device__ __forceinline__ void zeroC(float C[2][4][4]) {
    #pragma unroll
    for (int i = 0; i < 2; i++)
        #pragma unroll
        for (int j = 0; j < 4; j++)
            #pragma unroll
            for (int q = 0; q < 4; q++) C[i][j][q] = 0.f;
}
// cp.async one 128-dim x 128-ch fp16 weight chunk into ROWB-strided smem
__device__ __forceinline__ void cpW(uint32_t dstbase, const __half* __restrict__ src, int tid) {
    #pragma unroll
    for (int i = tid; i < 2048; i += 512) {
        uint32_t off = (i >> 4) * (ROWB * 2) + (i & 15) * 16;
        CP16(dstbase + off, (const char*)src + i * 16);
    }
}

// ---------------- P0: weights -> fp16 ----------------
__global__ __launch_bounds__(512) void attn_p0(
    const float* __restrict__ Wk, const float* __restrict__ Wv,
    const float* __restrict__ Wq)
{
    const float* src = (blockIdx.y == 0) ? Wk : (blockIdx.y == 1) ? Wv : Wq;
    const float4* W4 = (const float4*)src;
    int idx = blockIdx.x * 512 + threadIdx.x;       // grid.x = 32 -> 16384 float4
    float4 v = W4[idx];
    __half2 a = __floats2half2_rn(v.x, v.y), b = __floats2half2_rn(v.z, v.w);
    *(uint2*)(g_W16 + (size_t)blockIdx.y * 65536 + idx * 4) =
        make_uint2(*(uint32_t*)&a, *(uint32_t*)&b);
}

// ---------------- P1 ----------------
#define SMEM1 (6 * 128 * ROWB * 2 + 2048 * 4)

__global__ __launch_bounds__(512, 1) void attn_p1(
    const float* __restrict__ x,
    const float* __restrict__ bq, const float* __restrict__ bk,
    const float* __restrict__ bv)
{
    __half* xh  = (__half*)smraw;
    __half* w0  = xh + 128 * ROWB;       // Wk slot
    __half* w1  = w0 + 128 * ROWB;       // Wv slot
    __half* w2  = w1 + 128 * ROWB;       // Wq slot
    __half* ekT = w2 + 128 * ROWB;
    __half* vT  = ekT + 128 * ROWB;
    float* sb_bk = (float*)(vT + 128 * ROWB);
    float* sb_bv = sb_bk + 512;
    float* sb_bq = sb_bv + 512;
    float* sb_se = sb_bq + 512;          // [128 dim][4 tok-group] ek partial sums

    const uint32_t uxh = smem_u32(xh);
    const uint32_t uw0 = smem_u32(w0), uw1 = smem_u32(w1), uw2 = smem_u32(w2);
    const uint32_t uek = smem_u32(ekT), uvt = smem_u32(vT);

    const int tid = threadIdx.x, w = tid >> 5, lane = tid & 31;
    const int tile = blockIdx.x, b = blockIdx.y;
    const int bt = b * 128 + tile;
    const float* xb = x + (size_t)b * 128 * 16384 + (size_t)tile * 128;

    cpW(uw0, g_W16, tid);                 // Wk(0)
    cpW(uw1, g_W16 + 65536, tid);         // Wv(0)
    CPCOMMIT();

    sb_bk[tid] = bk[tid];  sb_bv[tid] = bv[tid];  sb_bq[tid] = bq[tid];

    // x tile -> fp16, layout [tok][ch]
    #pragma unroll
    for (int idx = tid; idx < 4096; idx += 512) {
        int c = idx >> 5, t = (idx & 31) << 2;
        float4 v = *(const float4*)(xb + (size_t)c * 16384 + t);
        xh[t * ROWB + c]       = __float2half_rn(v.x);
        xh[(t + 1) * ROWB + c] = __float2half_rn(v.y);
        xh[(t + 2) * ROWB + c] = __float2half_rn(v.z);
        xh[(t + 3) * ROWB + c] = __float2half_rn(v.w);
    }
    CPWAIT(0);
    __syncthreads();

    const int wm = (w >> 2) * 32;     // dim block (K/V proj)
    const int wn = (w & 3) * 32;      // token block

    for (int p = 0; p < 4; p++) {
        // ======== phase 1: fused K+V proj (shared x fragments) ========
        cpW(uw2, g_W16 + 131072 + p * 16384, tid);    // Wq(p)
        CPCOMMIT();

        {
            float CK[2][4][4], CV[2][4][4];
            zeroC(CK);  zeroC(CV);
            gemmKV(CK, CV, uw0, uw1, uxh, wm, wn);

            // K epilogue: exp -> ekT[dim][tok] (half2 stores) + register sums
            float se[4] = {0.f, 0.f, 0.f, 0.f};
            #pragma unroll
            for (int i = 0; i < 2; i++) {
                const int dim0 = wm + 16 * i + (lane >> 2);
                const float b0 = sb_bk[p * 128 + dim0];
                const float b8 = sb_bk[p * 128 + dim0 + 8];
                #pragma unroll
                for (int j = 0; j < 4; j++) {
                    const int tok = wn + 8 * j + ((lane & 3) << 1);
                    __half2 h01 = __floats2half2_rn(__expf(QSCALE * (CK[i][j][0] + b0)),
                                                    __expf(QSCALE * (CK[i][j][1] + b0)));
                    __half2 h23 = __floats2half2_rn(__expf(QSCALE * (CK[i][j][2] + b8)),
                                                    __expf(QSCALE * (CK[i][j][3] + b8)));
                    *(__half2*)(ekT + dim0 * ROWB + tok)       = h01;
                    *(__half2*)(ekT + (dim0 + 8) * ROWB + tok) = h23;
                    se[2 * i]     += __low2float(h01) + __high2float(h01);
                    se[2 * i + 1] += __low2float(h23) + __high2float(h23);
                }
            }
            #pragma unroll
            for (int q = 0; q < 4; q++) {
                se[q] += __shfl_xor_sync(0xffffffffu, se[q], 1);
                se[q] += __shfl_xor_sync(0xffffffffu, se[q], 2);
            }
            if ((lane & 3) == 0) {
                const int d0 = wm + (lane >> 2), g = w & 3;
                sb_se[d0 * 4 + g]        = se[0];
                sb_se[(d0 + 8) * 4 + g]  = se[1];
                sb_se[(d0 + 16) * 4 + g] = se[2];
                sb_se[(d0 + 24) * 4 + g] = se[3];
            }

            // V epilogue: +bv -> vT[dim][tok] (half2 stores)
            #pragma unroll
            for (int i = 0; i < 2; i++) {
                const int dim0 = wm + 16 * i + (lane >> 2);
                const float b0 = sb_bv[p * 128 + dim0];
                const float b8 = sb_bv[p * 128 + dim0 + 8];
                #pragma unroll
                for (int j = 0; j < 4; j++) {
                    const int tok = wn + 8 * j + ((lane & 3) << 1);
                    *(__half2*)(vT + dim0 * ROWB + tok) =
                        __floats2half2_rn(CV[i][j][0] + b0, CV[i][j][1] + b0);
                    *(__half2*)(vT + (dim0 + 8) * ROWB + tok) =
                        __floats2half2_rn(CV[i][j][2] + b8, CV[i][j][3] + b8);
                }
            }
        }
        CPWAIT(0);
        __syncthreads();

        // finalize per-dim ek sums -> transposed gmem
        if (tid < 128) {
            float4 v = *(const float4*)(sb_se + tid * 4);
            g_spart[(size_t)(p * 128 + tid) * 512 + bt] = v.x + v.y + v.z + v.w;
        }

        // ======== phase 2: ctx GEMM + Q proj (register softmax) ========
        if (p < 3) {
            cpW(uw0, g_W16 + (p + 1) * 16384, tid);           // Wk(p+1)
            cpW(uw1, g_W16 + 65536 + (p + 1) * 16384, tid);   // Wv(p+1)
            CPCOMMIT();
        }
        {   // ctx: per head, D[d][e] = sum_t ekT[d][t] * vT[e][t]
            const int hl = w >> 3, ww = w & 7;
            const int r0 = hl * 64 + (ww >> 1) * 16;
            const int e0 = hl * 64 + (ww & 1) * 32;
            float Cc[4][4];
            #pragma unroll
            for (int j = 0; j < 4; j++)
                #pragma unroll
                for (int q = 0; q < 4; q++) Cc[j][q] = 0.f;
            #pragma unroll
            for (int k0 = 0; k0 < 128; k0 += 16) {
                uint32_t a[4], b0[4], b1[4];
                ldmx4(a, a_addr(uek, r0, k0));
                ldmx4(b0, b_addr(uvt, e0, k0));
                ldmx4(b1, b_addr(uvt, e0 + 16, k0));
                mma16816(Cc[0], a, b0 + 0);  mma16816(Cc[1], a, b0 + 2);
                mma16816(Cc[2], a, b1 + 0);  mma16816(Cc[3], a, b1 + 2);
            }
            float* dst = g_ctxp + ((size_t)bt * 8 + 2 * p + hl) * 4096;
            const int d0 = (ww >> 1) * 16 + (lane >> 2);
            const int eb = (ww & 1) * 32;
            #pragma unroll
            for (int j = 0; j < 4; j++) {
                int e = eb + 8 * j + ((lane & 3) << 1);
                *(float2*)(dst + d0 * 64 + e)       = make_float2(Cc[j][0], Cc[j][1]);
                *(float2*)(dst + (d0 + 8) * 64 + e) = make_float2(Cc[j][2], Cc[j][3]);
            }
        }
        {   // Q proj: warp = 16 tokens x 64 dims (one full head)
            const int wqm = (w >> 1) * 16;     // token block
            const int hh  = (w & 1) * 64;      // head-half dim offset
            float Cq[8][4];
            #pragma unroll
            for (int j = 0; j < 8; j++)
                #pragma unroll
                for (int q = 0; q < 4; q++) Cq[j][q] = 0.f;
            #pragma unroll
            for (int k0 = 0; k0 < 128; k0 += 16) {
                uint32_t a[4], bb[4][4];
                ldmx4(a, a_addr(uxh, wqm, k0));
                #pragma unroll
                for (int jj = 0; jj < 4; jj++)
                    ldmx4(bb[jj], b_addr(uw2, hh + 16 * jj, k0));
                #pragma unroll
                for (int jj = 0; jj < 4; jj++) {
                    mma16816(Cq[2 * jj],     a, bb[jj] + 0);
                    mma16816(Cq[2 * jj + 1], a, bb[jj] + 2);
                }
            }
            // exp -> round to half; per-row sums of rounded values
            __half2 hv0[8], hv1[8];
            float s0 = 0.f, s1 = 0.f;
            #pragma unroll
            for (int jf = 0; jf < 8; jf++) {
                int dim = hh + 8 * jf + ((lane & 3) << 1);
                float b0 = sb_bq[p * 128 + dim], b1 = sb_bq[p * 128 + dim + 1];
                __half2 h01 = __floats2half2_rn(__expf(QSCALE * (Cq[jf][0] + b0)),
                                                __expf(QSCALE * (Cq[jf][1] + b1)));
                __half2 h23 = __floats2half2_rn(__expf(QSCALE * (Cq[jf][2] + b0)),
                                                __expf(QSCALE * (Cq[jf][3] + b1)));
                hv0[jf] = h01;  hv1[jf] = h23;
                s0 += __low2float(h01) + __high2float(h01);
                s1 += __low2float(h23) + __high2float(h23);
            }
            s0 += __shfl_xor_sync(0xffffffffu, s0, 1);
            s0 += __shfl_xor_sync(0xffffffffu, s0, 2);
            s1 += __shfl_xor_sync(0xffffffffu, s1, 1);
            s1 += __shfl_xor_sync(0xffffffffu, s1, 2);
            const float r0 = 1.f / s0, r1 = 1.f / s1;
            const int tok = wqm + (lane >> 2);
            __half* qdst = g_qs + ((size_t)bt * 4 + p) * 16384;
            #pragma unroll
            for (int jf = 0; jf < 8; jf++) {
                int dim = hh + 8 * jf + ((lane & 3) << 1);
                __half2 v0 = hv0[jf], v1 = hv1[jf];
                *(__half2*)(qdst + tok * 128 + dim) =
                    __floats2half2_rn(__low2float(v0) * r0, __high2float(v0) * r0);
                *(__half2*)(qdst + (tok + 8) * 128 + dim) =
                    __floats2half2_rn(__low2float(v1) * r1, __high2float(v1) * r1);
            }
        }
        CPWAIT(0);
        __syncthreads();   // protect ekT/vT/W slots before next chunk
    }
}

// ---------------- P2: fused reduce + normalize + fold Wo -> M ----------------
// grid (32 bh, 8 d-slices), 256 threads.
#define SMEM2 ((520 + 8 + 8192) * 4)

__global__ __launch_bounds__(256) void attn_p2(const float* __restrict__ Wo)
{
    float* ctx_s = (float*)smraw;      // [8][65] padded
    float* rS    = ctx_s + 520;        // [8]
    float* wo_s  = rS + 8;             // [128 o][64 e]
    const int bh = blockIdx.x, sl = blockIdx.y;
    const int b = bh >> 3, h = bh & 7;
    const int tid = threadIdx.x;

    // Wo slice -> smem (coalesced float4)
    for (int i = tid; i < 2048; i += 256) {
        int o = i >> 4, e4 = (i & 15) << 2;
        *(float4*)(wo_s + o * 64 + e4) = *(const float4*)(Wo + o * 512 + h * 64 + e4);
    }

    // ctx reduce over 128 tiles (coalesced 2KB per tile read)
    {
        const size_t base = (size_t)b * 128 * 32768 + (size_t)h * 4096 + sl * 512;
        const float* p0 = g_ctxp + base + tid;
        const float* p1 = p0 + 256;
        float s0 = 0.f, s1 = 0.f;
        #pragma unroll 8
        for (int t = 0; t < 128; t++) {
            s0 += p0[(size_t)t * 32768];
            s1 += p1[(size_t)t * 32768];
        }
        int i0 = tid, i1 = tid + 256;
        ctx_s[(i0 >> 6) * 65 + (i0 & 63)] = s0;
        ctx_s[(i1 >> 6) * 65 + (i1 & 63)] = s1;
    }

    // rS for this slice's 8 dims (contiguous reads from transposed spart)
    if (tid < 32) {
        const int d8 = tid >> 2, part = tid & 3;
        const float4* src = (const float4*)(g_spart
            + (size_t)(h * 64 + sl * 8 + d8) * 512 + b * 128 + part * 32);
        float s = 0.f;
        #pragma unroll
        for (int i = 0; i < 8; i++) {
            float4 v = src[i];
            s += v.x + v.y + v.z + v.w;
        }
        s += __shfl_xor_sync(0xffffffffu, s, 1);
        s += __shfl_xor_sync(0xffffffffu, s, 2);
        if (part == 0) rS[d8] = 1.f / s;
    }
    __syncthreads();

    // fold: M[o][d] = rS[d] * sum_e wo[o][e] * ctx[d][e]
    const size_t mb = (size_t)(b * 4 + (h >> 1)) * 16384 + (h & 1) * 64 + sl * 8;
    for (int i = tid; i < 1024; i += 256) {
        int o = i >> 3, d = i & 7;
        float s = 0.f;
        #pragma unroll 8
        for (int e = 0; e < 64; e++)
            s = fmaf(wo_s[o * 64 + e], ctx_s[d * 65 + e], s);
        g_Mh[mb + o * 128 + d] = __float2half_rn(s * rS[d]);
    }
}

// ---------------- P3: out = M * qn^T + bo (K=512, cp.async 3-deep) ----------------
#define SMEM3 (6 * 128 * ROWB * 2 + 128 * 4)

__global__ __launch_bounds__(512, 1) void attn_p3(
    const float* __restrict__ bo, float* __restrict__ out)
{
    __half* bufs = (__half*)smraw;     // m0,m1,m2,q0,q1,q2
    float* sb_bo = (float*)(bufs + 6 * 128 * ROWB);

    uint32_t um[3], uq[3];
    #pragma unroll
    for (int i = 0; i < 3; i++) {
        um[i] = smem_u32(bufs + i * 128 * ROWB);
        uq[i] = smem_u32(bufs + (3 + i) * 128 * ROWB);
    }

    const int tid = threadIdx.x, w = tid >> 5, lane = tid & 31;
    const int tile = blockIdx.x, b = blockIdx.y;
    const int bt = b * 128 + tile;

    if (tid < 128) sb_bo[tid] = bo[tid];

    // prologue: chunks 0 and 1
    #pragma unroll
    for (int c = 0; c < 2; c++) {
        const char* msrc = (const char*)(g_Mh + (size_t)(b * 4 + c) * 16384);
        const char* qsrc = (const char*)(g_qs + (size_t)(bt * 4 + c) * 16384);
        #pragma unroll
        for (int i = tid; i < 2048; i += 512) {
            uint32_t off = (i >> 4) * (ROWB * 2) + (i & 15) * 16;
            CP16(um[c] + off, msrc + i * 16);
            CP16(uq[c] + off, qsrc + i * 16);
        }
        CPCOMMIT();
    }

    const int wm = (w >> 2) * 32;   // o block
    const int wn = (w & 3) * 32;    // token block
    float Co[2][4][4];
    zeroC(Co);

    for (int p = 0; p < 4; p++) {
        const int cur = p % 3;
        if (p < 2) {
            const int nxt = (p + 2) % 3;
            const char* msrc = (const char*)(g_Mh + (size_t)(b * 4 + p + 2) * 16384);
            const char* qsrc = (const char*)(g_qs + (size_t)(bt * 4 + p + 2) * 16384);
            #pragma unroll
            for (int i = tid; i < 2048; i += 512) {
                uint32_t off = (i >> 4) * (ROWB * 2) + (i & 15) * 16;
                CP16(um[nxt] + off, msrc + i * 16);
                CP16(uq[nxt] + off, qsrc + i * 16);
            }
            CPCOMMIT();
        }
        if (p < 2)       CPWAIT(2);
        else if (p == 2) CPWAIT(1);
        else             CPWAIT(0);
        __syncthreads();
        gemm32x32(Co, um[cur], uq[cur], wm, wn);
        __syncthreads();
    }

    float* ob = out + (size_t)b * 128 * 16384 + (size_t)tile * 128;
    #pragma unroll
    for (int i = 0; i < 2; i++)
        #pragma unroll
        for (int j = 0; j < 4; j++) {
            int o = wm + 16 * i + (lane >> 2);
            int t = wn + 8 * j + ((lane & 3) << 1);
            float bo0 = sb_bo[o], bo8 = sb_bo[o + 8];
            *(float2*)(ob + (size_t)o * 16384 + t) =
                make_float2(Co[i][j][0] + bo0, Co[i][j][1] + bo0);
            *(float2*)(ob + (size_t)(o + 8) * 16384 + t) =
                make_float2(Co[i][j][2] + bo8, Co[i][j][3] + bo8);
        }
}

// ---------------------------------------------------------------------------
extern "C" void kernel_launch(void* const* d_in, const int* in_sizes, int n_in,
                              void* d_out, int out_size)
{
    const float* x  = (const float*)d_in[0];
    const float* Wq = (const float*)d_in[1];
    const float* bq = (const float*)d_in[2];
    const float* Wk = (const float*)d_in[3];
    const float* bk = (const float*)d_in[4];
    const float* Wv = (const float*)d_in[5];
    const float* bv = (const float*)d_in[6];
    const float* Wo = (const float*)d_in[7];
    const float* bo = (const float*)d_in[8];
    float* out = (float*)d_out;

    cudaFuncSetAttribute(attn_p1, cudaFuncAttributeMaxDynamicSharedMemorySize, SMEM1);
    cudaFuncSetAttribute(attn_p2, cudaFuncAttributeMaxDynamicSharedMemorySize, SMEM2);
    cudaFuncSetAttribute(attn_p3, cudaFuncAttributeMaxDynamicSharedMemorySize, SMEM3);

    attn_p0<<<dim3(32, 3), 512>>>(Wk, Wv, Wq);
    attn_p1<<<dim3(128, 4), 512, SMEM1>>>(x, bq, bk, bv);
    attn_p2<<<dim3(32, 8), 256, SMEM2>>>(Wo);
    attn_p3<<<dim3(128, 4), 512, SMEM3>>>(bo, out);
}

// round 16
// speedup vs baseline: 1.0614x; 1.0614x over previous
#include <cuda_runtime.h>
#include <cuda_fp16.h>
#include <cstdint>

// ImageLinearAttention via warp-level mma.sync (m16n8k16 f16->f32), ldmatrix
// fragment loads, cp.async weight feed. B=4, C=128, n=16384, HEADS=8, KD=VD=64.
//
// P0: convert Wk/Wv/Wq to fp16 once.
// P1: 256-thread CTAs, 2 resident/SM. CTA = (tile, head-half): per chunk p it
//     handles head 2p+hh only (64-dim W slices): K proj -> exp -> ekT + sums;
//     V proj -> vT; ctx partials; q proj (warp = 16 tok x full head) -> shfl
//     softmax -> qn. 2 W slots, round-12 rotation.
// P2: 256 CTAs (bh x 8 d-slices): reduce ctx 128->1, rS, fold Wo -> M (fp16).
// P3: pure GEMM out = M*qn^T + bo, K=512, cp.async 3-deep pipelined tiles.

#define ROWB 136                      // halves per smem row (128 + 8 pad)
#define QSCALE 0.35355339059327373f   // 64^-0.25

__device__ float  g_ctxp[(size_t)512 * 8 * 64 * 64];            // [bt][head][d][e]
__device__ float  g_spart[512 * 512];                            // [dim512][bt]
__device__ __align__(128) __half g_qs[(size_t)512 * 4 * 16384];  // [bt][p][tok][dim]
__device__ __align__(128) __half g_Mh[4 * 4 * 16384];            // [b][p][o][hd128]
__device__ __align__(128) __half g_W16[3 * 512 * 128];           // [kvq][dim][ch] fp16

extern __shared__ char smraw[];

// ---------------- PTX helpers ----------------
__device__ __forceinline__ uint32_t smem_u32(const void* p) {
    uint32_t a;
    asm("{ .reg .u64 t; cvta.to.shared.u64 t, %1; cvt.u32.u64 %0, t; }" : "=r"(a) : "l"(p));
    return a;
}
__device__ __forceinline__ void mma16816(float c[4], const uint32_t a[4],
                                         const uint32_t b[2]) {
    asm volatile(
        "mma.sync.aligned.m16n8k16.row.col.f32.f16.f16.f32 "
        "{%0,%1,%2,%3}, {%4,%5,%6,%7}, {%8,%9}, {%0,%1,%2,%3};"
        : "+f"(c[0]), "+f"(c[1]), "+f"(c[2]), "+f"(c[3])
        : "r"(a[0]), "r"(a[1]), "r"(a[2]), "r"(a[3]), "r"(b[0]), "r"(b[1]));
}
__device__ __forceinline__ void ldmx4(uint32_t r[4], uint32_t addr) {
    asm volatile("ldmatrix.sync.aligned.m8n8.x4.shared.b16 {%0,%1,%2,%3}, [%4];"
        : "=r"(r[0]), "=r"(r[1]), "=r"(r[2]), "=r"(r[3]) : "r"(addr));
}
#define CP16(dst, src) asm volatile("cp.async.cg.shared.global [%0], [%1], 16;" :: "r"(dst), "l"(src))
#define CPCOMMIT()     asm volatile("cp.async.commit_group;" ::: "memory")
#define CPWAIT(n)      asm volatile("cp.async.wait_group %0;" :: "n"(n) : "memory")

__device__ __forceinline__ uint32_t a_addr(uint32_t base, int r0, int k0) {
    const int l = threadIdx.x & 31;
    return base + ((r0 + (l & 15)) * ROWB + k0 + ((l >> 4) << 3)) * 2;
}
__device__ __forceinline__ uint32_t b_addr(uint32_t base, int n0, int k0) {
    const int l = threadIdx.x & 31;
    return base + ((n0 + (l & 7) + ((l >> 4) << 3)) * ROWB + k0 + (((l >> 3) & 1) << 3)) * 2;
}
// 32x32 warp-tile GEMM over K=128, fragment double-buffered.
__device__ __forceinline__ void gemm32x32(float C[2][4][4], uint32_t A, uint32_t B,
                                          int wm, int wn) {
    uint32_t a0[2][4], a1[2][4], b0[2][4], b1[2][4];
    ldmx4(a0[0], a_addr(A, wm, 0));
    ldmx4(a1[0], a_addr(A, wm + 16, 0));
    ldmx4(b0[0], b_addr(B, wn, 0));
    ldmx4(b1[0], b_addr(B, wn + 16, 0));
    #pragma unroll
    for (int s = 0; s < 8; s++) {
        const int cur = s & 1, nxt = cur ^ 1;
        if (s < 7) {
            const int k1 = (s + 1) << 4;
            ldmx4(a0[nxt], a_addr(A, wm, k1));
            ldmx4(a1[nxt], a_addr(A, wm + 16, k1));
            ldmx4(b0[nxt], b_addr(B, wn, k1));
            ldmx4(b1[nxt], b_addr(B, wn + 16, k1));
        }
        mma16816(C[0][0], a0[cur], b0[cur] + 0);  mma16816(C[0][1], a0[cur], b0[cur] + 2);
        mma16816(C[0][2], a0[cur], b1[cur] + 0);  mma16816(C[0][3], a0[cur], b1[cur] + 2);
        mma16816(C[1][0], a1[cur], b0[cur] + 0);  mma16816(C[1][1], a1[cur], b0[cur] + 2);
        mma16816(C[1][2], a1[cur], b1[cur] + 0);  mma16816(C[1][3], a1[cur], b1[cur] + 2);
    }
}
__device__ __forceinline__ void zeroC(float C[2][4][4]) {
    #pragma unroll
    for (int i = 0; i < 2; i++)
        #pragma unroll
        for (int j = 0; j < 4; j++)
            #pragma unroll
            for (int q = 0; q < 4; q++) C[i][j][q] = 0.f;
}
// cp.async one 64-dim x 128-ch fp16 weight slice into ROWB-strided smem (256 thr)
__device__ __forceinline__ void cpW64(uint32_t dstbase, const __half* __restrict__ src, int tid) {
    #pragma unroll
    for (int i = tid; i < 1024; i += 256) {
        uint32_t off = (i >> 4) * (ROWB * 2) + (i & 15) * 16;
        CP16(dstbase + off, (const char*)src + i * 16);
    }
}

// ---------------- P0: weights -> fp16 ----------------
__global__ __launch_bounds__(512) void attn_p0(
    const float* __restrict__ Wk, const float* __restrict__ Wv,
    const float* __restrict__ Wq)
{
    const float* src = (blockIdx.y == 0) ? Wk : (blockIdx.y == 1) ? Wv : Wq;
    const float4* W4 = (const float4*)src;
    int idx = blockIdx.x * 512 + threadIdx.x;       // grid.x = 32 -> 16384 float4
    float4 v = W4[idx];
    __half2 a = __floats2half2_rn(v.x, v.y), b = __floats2half2_rn(v.z, v.w);
    *(uint2*)(g_W16 + (size_t)blockIdx.y * 65536 + idx * 4) =
        make_uint2(*(uint32_t*)&a, *(uint32_t*)&b);
}

// ---------------- P1 (256 threads, 2 CTAs/SM, head-half split) ----------------
// smem: xh(34816) + 2 W slots(2*17408) + ekT(17408) + vT(17408) + bias(6144) + se(1024)
#define SMEM1 (34816 + 2 * 17408 + 17408 + 17408 + 6144 + 1024)

__global__ __launch_bounds__(256, 2) void attn_p1(
    const float* __restrict__ x,
    const float* __restrict__ bq, const float* __restrict__ bk,
    const float* __restrict__ bv)
{
    __half* xh  = (__half*)smraw;            // [128 tok][ROWB]
    __half* w0  = xh + 128 * ROWB;           // W slot 0 [64][ROWB]
    __half* w1  = w0 + 64 * ROWB;            // W slot 1
    __half* ekT = w1 + 64 * ROWB;            // [64 dim][ROWB tok]
    __half* vT  = ekT + 64 * ROWB;
    float* sb_bk = (float*)(vT + 64 * ROWB);
    float* sb_bv = sb_bk + 512;
    float* sb_bq = sb_bv + 512;
    float* sb_se = sb_bq + 512;              // [64 dim][4 tok-group]

    const uint32_t uxh = smem_u32(xh);
    const uint32_t uw0 = smem_u32(w0), uw1 = smem_u32(w1);
    const uint32_t uek = smem_u32(ekT), uvt = smem_u32(vT);

    const int tid = threadIdx.x, w = tid >> 5, lane = tid & 31;
    const int tile = blockIdx.x, b = blockIdx.y, hh = blockIdx.z;
    const int bt = b * 128 + tile;
    const float* xb = x + (size_t)b * 128 * 16384 + (size_t)tile * 128;

    // weight slice base (in halves): [kvq]*65536 + (p*128 + hh*64)*128
    const int hoff = hh * 64 * 128;

    cpW64(uw0, g_W16 + hoff, tid);           // Wk(0) slice -> slot 0
    CPCOMMIT();

    sb_bk[tid] = bk[tid];        sb_bk[tid + 256] = bk[tid + 256];
    sb_bv[tid] = bv[tid];        sb_bv[tid + 256] = bv[tid + 256];
    sb_bq[tid] = bq[tid];        sb_bq[tid + 256] = bq[tid + 256];

    // x tile -> fp16, layout [tok][ch]
    #pragma unroll
    for (int idx = tid; idx < 4096; idx += 256) {
        int c = idx >> 5, t = (idx & 31) << 2;
        float4 v = *(const float4*)(xb + (size_t)c * 16384 + t);
        xh[t * ROWB + c]       = __float2half_rn(v.x);
        xh[(t + 1) * ROWB + c] = __float2half_rn(v.y);
        xh[(t + 2) * ROWB + c] = __float2half_rn(v.z);
        xh[(t + 3) * ROWB + c] = __float2half_rn(v.w);
    }
    CPWAIT(0);
    __syncthreads();

    const int wm = (w >> 2) * 32;     // dim block within the 64-dim head slice
    const int wn = (w & 3) * 32;      // token block

    for (int p = 0; p < 4; p++) {
        const int gd = p * 128 + hh * 64;          // global dim base of this head
        const uint32_t usk = ((3 * p) & 1) ? uw1 : uw0;       // Wk slot
        const uint32_t usv = ((3 * p + 1) & 1) ? uw1 : uw0;   // Wv slot
        const uint32_t usq = ((3 * p + 2) & 1) ? uw1 : uw0;   // Wq slot
        const uint32_t unk = ((3 * p + 3) & 1) ? uw1 : uw0;   // next Wk slot

        float C[2][4][4];

        // ---- phase A: K proj, D[dim64][tok128] ----
        cpW64(usv, g_W16 + 65536 + p * 16384 + hoff, tid);    // Wv(p) slice
        CPCOMMIT();
        zeroC(C);
        gemm32x32(C, usk, uxh, wm, wn);
        {
            float se[4] = {0.f, 0.f, 0.f, 0.f};
            #pragma unroll
            for (int i = 0; i < 2; i++) {
                const int dim0 = wm + 16 * i + (lane >> 2);
                const float b0 = sb_bk[gd + dim0];
                const float b8 = sb_bk[gd + dim0 + 8];
                #pragma unroll
                for (int j = 0; j < 4; j++) {
                    const int tok = wn + 8 * j + ((lane & 3) << 1);
                    __half2 h01 = __floats2half2_rn(__expf(QSCALE * (C[i][j][0] + b0)),
                                                    __expf(QSCALE * (C[i][j][1] + b0)));
                    __half2 h23 = __floats2half2_rn(__expf(QSCALE * (C[i][j][2] + b8)),
                                                    __expf(QSCALE * (C[i][j][3] + b8)));
                    *(__half2*)(ekT + dim0 * ROWB + tok)       = h01;
                    *(__half2*)(ekT + (dim0 + 8) * ROWB + tok) = h23;
                    se[2 * i]     += __low2float(h01) + __high2float(h01);
                    se[2 * i + 1] += __low2float(h23) + __high2float(h23);
                }
            }
            #pragma unroll
            for (int q = 0; q < 4; q++) {
                se[q] += __shfl_xor_sync(0xffffffffu, se[q], 1);
                se[q] += __shfl_xor_sync(0xffffffffu, se[q], 2);
            }
            if ((lane & 3) == 0) {
                const int d0 = wm + (lane >> 2), g = w & 3;
                sb_se[d0 * 4 + g]        = se[0];
                sb_se[(d0 + 8) * 4 + g]  = se[1];
                sb_se[(d0 + 16) * 4 + g] = se[2];
                sb_se[(d0 + 24) * 4 + g] = se[3];
            }
        }
        CPWAIT(0);
        __syncthreads();

        // finalize per-dim ek sums -> transposed gmem
        if (tid < 64) {
            float4 v = *(const float4*)(sb_se + tid * 4);
            g_spart[(size_t)(gd + tid) * 512 + bt] = v.x + v.y + v.z + v.w;
        }

        // ---- phase B: V proj, D[dim64][tok128] ----
        cpW64(usq, g_W16 + 131072 + p * 16384 + hoff, tid);   // Wq(p) slice
        CPCOMMIT();
        zeroC(C);
        gemm32x32(C, usv, uxh, wm, wn);
        #pragma unroll
        for (int i = 0; i < 2; i++) {
            const int dim0 = wm + 16 * i + (lane >> 2);
            const float b0 = sb_bv[gd + dim0];
            const float b8 = sb_bv[gd + dim0 + 8];
            #pragma unroll
            for (int j = 0; j < 4; j++) {
                const int tok = wn + 8 * j + ((lane & 3) << 1);
                *(__half2*)(vT + dim0 * ROWB + tok) =
                    __floats2half2_rn(C[i][j][0] + b0, C[i][j][1] + b0);
                *(__half2*)(vT + (dim0 + 8) * ROWB + tok) =
                    __floats2half2_rn(C[i][j][2] + b8, C[i][j][3] + b8);
            }
        }
        CPWAIT(0);
        __syncthreads();

        // ---- phase C: ctx GEMM + Q proj (register softmax) ----
        if (p < 3) {
            cpW64(unk, g_W16 + (p + 1) * 16384 + hoff, tid);  // Wk(p+1) slice
            CPCOMMIT();
        }
        {   // ctx: D[d64][e64] = sum_t ekT[d][t] * vT[e][t]; warp = 16d x 32e
            const int r0 = (w >> 1) * 16;
            const int e0 = (w & 1) * 32;
            float Cc[4][4];
            #pragma unroll
            for (int j = 0; j < 4; j++)
                #pragma unroll
                for (int q = 0; q < 4; q++) Cc[j][q] = 0.f;
            #pragma unroll
            for (int k0 = 0; k0 < 128; k0 += 16) {
                uint32_t a[4], b0[4], b1[4];
                ldmx4(a, a_addr(uek, r0, k0));
                ldmx4(b0, b_addr(uvt, e0, k0));
                ldmx4(b1, b_addr(uvt, e0 + 16, k0));
                mma16816(Cc[0], a, b0 + 0);  mma16816(Cc[1], a, b0 + 2);
                mma16816(Cc[2], a, b1 + 0);  mma16816(Cc[3], a, b1 + 2);
            }
            float* dst = g_ctxp + ((size_t)bt * 8 + 2 * p + hh) * 4096;
            const int d0 = r0 + (lane >> 2);
            #pragma unroll
            for (int j = 0; j < 4; j++) {
                int e = e0 + 8 * j + ((lane & 3) << 1);
                *(float2*)(dst + d0 * 64 + e)       = make_float2(Cc[j][0], Cc[j][1]);
                *(float2*)(dst + (d0 + 8) * 64 + e) = make_float2(Cc[j][2], Cc[j][3]);
            }
        }
        {   // Q proj: warp = 16 tokens x full 64-dim head
            const int wqm = w * 16;            // token block (8 warps x 16 = 128)
            float Cq[8][4];
            #pragma unroll
            for (int j = 0; j < 8; j++)
                #pragma unroll
                for (int q = 0; q < 4; q++) Cq[j][q] = 0.f;
            #pragma unroll
            for (int k0 = 0; k0 < 128; k0 += 16) {
                uint32_t a[4], bb[4][4];
                ldmx4(a, a_addr(uxh, wqm, k0));
                #pragma unroll
                for (int jj = 0; jj < 4; jj++)
                    ldmx4(bb[jj], b_addr(usq, 16 * jj, k0));
                #pragma unroll
                for (int jj = 0; jj < 4; jj++) {
                    mma16816(Cq[2 * jj],     a, bb[jj] + 0);
                    mma16816(Cq[2 * jj + 1], a, bb[jj] + 2);
                }
            }
            // exp -> round to half; per-row sums of rounded values
            __half2 hv0[8], hv1[8];
            float s0 = 0.f, s1 = 0.f;
            #pragma unroll
            for (int jf = 0; jf < 8; jf++) {
                int dim = 8 * jf + ((lane & 3) << 1);
                float b0 = sb_bq[gd + dim], b1 = sb_bq[gd + dim + 1];
                __half2 h01 = __floats2half2_rn(__expf(QSCALE * (Cq[jf][0] + b0)),
                                                __expf(QSCALE * (Cq[jf][1] + b1)));
                __half2 h23 = __floats2half2_rn(__expf(QSCALE * (Cq[jf][2] + b0)),
                                                __expf(QSCALE * (Cq[jf][3] + b1)));
                hv0[jf] = h01;  hv1[jf] = h23;
                s0 += __low2float(h01) + __high2float(h01);
                s1 += __low2float(h23) + __high2float(h23);
            }
            s0 += __shfl_xor_sync(0xffffffffu, s0, 1);
            s0 += __shfl_xor_sync(0xffffffffu, s0, 2);
            s1 += __shfl_xor_sync(0xffffffffu, s1, 1);
            s1 += __shfl_xor_sync(0xffffffffu, s1, 2);
            const float r0 = 1.f / s0, r1 = 1.f / s1;
            const int tok = wqm + (lane >> 2);
            __half* qdst = g_qs + ((size_t)bt * 4 + p) * 16384 + hh * 64;
            #pragma unroll
            for (int jf = 0; jf < 8; jf++) {
                int dim = 8 * jf + ((lane & 3) << 1);
                __half2 v0 = hv0[jf], v1 = hv1[jf];
                *(__half2*)(qdst + tok * 128 + dim) =
                    __floats2half2_rn(__low2float(v0) * r0, __high2float(v0) * r0);
                *(__half2*)(qdst + (tok + 8) * 128 + dim) =
                    __floats2half2_rn(__low2float(v1) * r1, __high2float(v1) * r1);
            }
        }
        CPWAIT(0);
        __syncthreads();   // protect ekT/vT/W slots before next chunk
    }
}

// ---------------- P2: fused reduce + normalize + fold Wo -> M ----------------
// grid (32 bh, 8 d-slices), 256 threads.
#define SMEM2 ((520 + 8 + 8192) * 4)

__global__ __launch_bounds__(256) void attn_p2(const float* __restrict__ Wo)
{
    float* ctx_s = (float*)smraw;      // [8][65] padded
    float* rS    = ctx_s + 520;        // [8]
    float* wo_s  = rS + 8;             // [128 o][64 e]
    const int bh = blockIdx.x, sl = blockIdx.y;
    const int b = bh >> 3, h = bh & 7;
    const int tid = threadIdx.x;

    // Wo slice -> smem (coalesced float4)
    for (int i = tid; i < 2048; i += 256) {
        int o = i >> 4, e4 = (i & 15) << 2;
        *(float4*)(wo_s + o * 64 + e4) = *(const float4*)(Wo + o * 512 + h * 64 + e4);
    }

    // ctx reduce over 128 tiles (coalesced 2KB per tile read)
    {
        const size_t base = (size_t)b * 128 * 32768 + (size_t)h * 4096 + sl * 512;
        const float* p0 = g_ctxp + base + tid;
        const float* p1 = p0 + 256;
        float s0 = 0.f, s1 = 0.f;
        #pragma unroll 8
        for (int t = 0; t < 128; t++) {
            s0 += p0[(size_t)t * 32768];
            s1 += p1[(size_t)t * 32768];
        }
        int i0 = tid, i1 = tid + 256;
        ctx_s[(i0 >> 6) * 65 + (i0 & 63)] = s0;
        ctx_s[(i1 >> 6) * 65 + (i1 & 63)] = s1;
    }

    // rS for this slice's 8 dims (contiguous reads from transposed spart)
    if (tid < 32) {
        const int d8 = tid >> 2, part = tid & 3;
        const float4* src = (const float4*)(g_spart
            + (size_t)(h * 64 + sl * 8 + d8) * 512 + b * 128 + part * 32);
        float s = 0.f;
        #pragma unroll
        for (int i = 0; i < 8; i++) {
            float4 v = src[i];
            s += v.x + v.y + v.z + v.w;
        }
        s += __shfl_xor_sync(0xffffffffu, s, 1);
        s += __shfl_xor_sync(0xffffffffu, s, 2);
        if (part == 0) rS[d8] = 1.f / s;
    }
    __syncthreads();

    // fold: M[o][d] = rS[d] * sum_e wo[o][e] * ctx[d][e]
    const size_t mb = (size_t)(b * 4 + (h >> 1)) * 16384 + (h & 1) * 64 + sl * 8;
    for (int i = tid; i < 1024; i += 256) {
        int o = i >> 3, d = i & 7;
        float s = 0.f;
        #pragma unroll 8
        for (int e = 0; e < 64; e++)
            s = fmaf(wo_s[o * 64 + e], ctx_s[d * 65 + e], s);
        g_Mh[mb + o * 128 + d] = __float2half_rn(s * rS[d]);
    }
}

// ---------------- P3: out = M * qn^T + bo (K=512, cp.async 3-deep) ----------------
#define SMEM3 (6 * 128 * ROWB * 2 + 128 * 4)

__global__ __launch_bounds__(512, 1) void attn_p3(
    const float* __restrict__ bo, float* __restrict__ out)
{
    __half* bufs = (__half*)smraw;     // m0,m1,m2,q0,q1,q2
    float* sb_bo = (float*)(bufs + 6 * 128 * ROWB);

    uint32_t um[3], uq[3];
    #pragma unroll
    for (int i = 0; i < 3; i++) {
        um[i] = smem_u32(bufs + i * 128 * ROWB);
        uq[i] = smem_u32(bufs + (3 + i) * 128 * ROWB);
    }

    const int tid = threadIdx.x, w = tid >> 5, lane = tid & 31;
    const int tile = blockIdx.x, b = blockIdx.y;
    const int bt = b * 128 + tile;

    if (tid < 128) sb_bo[tid] = bo[tid];

    // prologue: chunks 0 and 1
    #pragma unroll
    for (int c = 0; c < 2; c++) {
        const char* msrc = (const char*)(g_Mh + (size_t)(b * 4 + c) * 16384);
        const char* qsrc = (const char*)(g_qs + (size_t)(bt * 4 + c) * 16384);
        #pragma unroll
        for (int i = tid; i < 2048; i += 512) {
            uint32_t off = (i >> 4) * (ROWB * 2) + (i & 15) * 16;
            CP16(um[c] + off, msrc + i * 16);
            CP16(uq[c] + off, qsrc + i * 16);
        }
        CPCOMMIT();
    }

    const int wm = (w >> 2) * 32;   // o block
    const int wn = (w & 3) * 32;    // token block
    float Co[2][4][4];
    zeroC(Co);

    for (int p = 0; p < 4; p++) {
        const int cur = p % 3;
        if (p < 2) {
            const int nxt = (p + 2) % 3;
            const char* msrc = (const char*)(g_Mh + (size_t)(b * 4 + p + 2) * 16384);
            const char* qsrc = (const char*)(g_qs + (size_t)(bt * 4 + p + 2) * 16384);
            #pragma unroll
            for (int i = tid; i < 2048; i += 512) {
                uint32_t off = (i >> 4) * (ROWB * 2) + (i & 15) * 16;
                CP16(um[nxt] + off, msrc + i * 16);
                CP16(uq[nxt] + off, qsrc + i * 16);
            }
            CPCOMMIT();
        }
        if (p < 2)       CPWAIT(2);
        else if (p == 2) CPWAIT(1);
        else             CPWAIT(0);
        __syncthreads();
        gemm32x32(Co, um[cur], uq[cur], wm, wn);
        __syncthreads();
    }

    float* ob = out + (size_t)b * 128 * 16384 + (size_t)tile * 128;
    #pragma unroll
    for (int i = 0; i < 2; i++)
        #pragma unroll
        for (int j = 0; j < 4; j++) {
            int o = wm + 16 * i + (lane >> 2);
            int t = wn + 8 * j + ((lane & 3) << 1);
            float bo0 = sb_bo[o], bo8 = sb_bo[o + 8];
            *(float2*)(ob + (size_t)o * 16384 + t) =
                make_float2(Co[i][j][0] + bo0, Co[i][j][1] + bo0);
            *(float2*)(ob + (size_t)(o + 8) * 16384 + t) =
                make_float2(Co[i][j][2] + bo8, Co[i][j][3] + bo8);
        }
}

// ---------------------------------------------------------------------------
extern "C" void kernel_launch(void* const* d_in, const int* in_sizes, int n_in,
                              void* d_out, int out_size)
{
    const float* x  = (const float*)d_in[0];
    const float* Wq = (const float*)d_in[1];
    const float* bq = (const float*)d_in[2];
    const float* Wk = (const float*)d_in[3];
    const float* bk = (const float*)d_in[4];
    const float* Wv = (const float*)d_in[5];
    const float* bv = (const float*)d_in[6];
    const float* Wo = (const float*)d_in[7];
    const float* bo = (const float*)d_in[8];
    float* out = (float*)d_out;

    cudaFuncSetAttribute(attn_p1, cudaFuncAttributeMaxDynamicSharedMemorySize, SMEM1);
    cudaFuncSetAttribute(attn_p2, cudaFuncAttributeMaxDynamicSharedMemorySize, SMEM2);
    cudaFuncSetAttribute(attn_p3, cudaFuncAttributeMaxDynamicSharedMemorySize, SMEM3);

    attn_p0<<<dim3(32, 3), 512>>>(Wk, Wv, Wq);
    attn_p1<<<dim3(128, 4, 2), 256, SMEM1>>>(x, bq, bk, bv);
    attn_p2<<<dim3(32, 8), 256, SMEM2>>>(Wo);
    attn_p3<<<dim3(128, 4), 512, SMEM3>>>(bo, out);
}

// round 17
// speedup vs baseline: 1.0721x; 1.0100x over previous
#include <cuda_runtime.h>
#include <cuda_fp16.h>
#include <cstdint>

// ImageLinearAttention via warp-level mma.sync (m16n8k16 f16->f32), ldmatrix
// fragment loads, cp.async weight feed. B=4, C=128, n=16384, HEADS=8, KD=VD=64.
//
// P0: convert Wk/Wv/Wq to fp16 once.
// P1: 256-thread CTAs, 2 resident/SM. CTA = (tile, head-half): per chunk p it
//     handles head 2p+hh only (64-dim W slices): K proj -> exp -> ekT + sums;
//     V proj -> vT; ctx partials; q proj (warp = 16 tok x full head) -> shfl
//     softmax -> qn. 2 W slots.
// P2: 256 CTAs (bh x 8 d-slices): reduce ctx 128->1, rS, fold Wo -> M (fp16).
// P3: 256-thread CTAs, 2 resident/SM. CTA = (tile, b, tok-half): out = M*qn^T
//     + bo over K=512, cp.async 2-deep; M duplicated (L2), qn read once.

#define ROWB 136                      // halves per smem row (128 + 8 pad)
#define QSCALE 0.35355339059327373f   // 64^-0.25

__device__ float  g_ctxp[(size_t)512 * 8 * 64 * 64];            // [bt][head][d][e]
__device__ float  g_spart[512 * 512];                            // [dim512][bt]
__device__ __align__(128) __half g_qs[(size_t)512 * 4 * 16384];  // [bt][p][tok][dim]
__device__ __align__(128) __half g_Mh[4 * 4 * 16384];            // [b][p][o][hd128]
__device__ __align__(128) __half g_W16[3 * 512 * 128];           // [kvq][dim][ch] fp16

extern __shared__ char smraw[];

// ---------------- PTX helpers ----------------
__device__ __forceinline__ uint32_t smem_u32(const void* p) {
    uint32_t a;
    asm("{ .reg .u64 t; cvta.to.shared.u64 t, %1; cvt.u32.u64 %0, t; }" : "=r"(a) : "l"(p));
    return a;
}
__device__ __forceinline__ void mma16816(float c[4], const uint32_t a[4],
                                         const uint32_t b[2]) {
    asm volatile(
        "mma.sync.aligned.m16n8k16.row.col.f32.f16.f16.f32 "
        "{%0,%1,%2,%3}, {%4,%5,%6,%7}, {%8,%9}, {%0,%1,%2,%3};"
        : "+f"(c[0]), "+f"(c[1]), "+f"(c[2]), "+f"(c[3])
        : "r"(a[0]), "r"(a[1]), "r"(a[2]), "r"(a[3]), "r"(b[0]), "r"(b[1]));
}
__device__ __forceinline__ void ldmx4(uint32_t r[4], uint32_t addr) {
    asm volatile("ldmatrix.sync.aligned.m8n8.x4.shared.b16 {%0,%1,%2,%3}, [%4];"
        : "=r"(r[0]), "=r"(r[1]), "=r"(r[2]), "=r"(r[3]) : "r"(addr));
}
#define CP16(dst, src) asm volatile("cp.async.cg.shared.global [%0], [%1], 16;" :: "r"(dst), "l"(src))
#define CPCOMMIT()     asm volatile("cp.async.commit_group;" ::: "memory")
#define CPWAIT(n)      asm volatile("cp.async.wait_group %0;" :: "n"(n) : "memory")

__device__ __forceinline__ uint32_t a_addr(uint32_t base, int r0, int k0) {
    const int l = threadIdx.x & 31;
    return base + ((r0 + (l & 15)) * ROWB + k0 + ((l >> 4) << 3)) * 2;
}
__device__ __forceinline__ uint32_t b_addr(uint32_t base, int n0, int k0) {
    const int l = threadIdx.x & 31;
    return base + ((n0 + (l & 7) + ((l >> 4) << 3)) * ROWB + k0 + (((l >> 3) & 1) << 3)) * 2;
}
// 32x32 warp-tile GEMM over K=128, fragment double-buffered.
__device__ __forceinline__ void gemm32x32(float C[2][4][4], uint32_t A, uint32_t B,
                                          int wm, int wn) {
    uint32_t a0[2][4], a1[2][4], b0[2][4], b1[2][4];
    ldmx4(a0[0], a_addr(A, wm, 0));
    ldmx4(a1[0], a_addr(A, wm + 16, 0));
    ldmx4(b0[0], b_addr(B, wn, 0));
    ldmx4(b1[0], b_addr(B, wn + 16, 0));
    #pragma unroll
    for (int s = 0; s < 8; s++) {
        const int cur = s & 1, nxt = cur ^ 1;
        if (s < 7) {
            const int k1 = (s + 1) << 4;
            ldmx4(a0[nxt], a_addr(A, wm, k1));
            ldmx4(a1[nxt], a_addr(A, wm + 16, k1));
            ldmx4(b0[nxt], b_addr(B, wn, k1));
            ldmx4(b1[nxt], b_addr(B, wn + 16, k1));
        }
        mma16816(C[0][0], a0[cur], b0[cur] + 0);  mma16816(C[0][1], a0[cur], b0[cur] + 2);
        mma16816(C[0][2], a0[cur], b1[cur] + 0);  mma16816(C[0][3], a0[cur], b1[cur] + 2);
        mma16816(C[1][0], a1[cur], b0[cur] + 0);  mma16816(C[1][1], a1[cur], b0[cur] + 2);
        mma16816(C[1][2], a1[cur], b1[cur] + 0);  mma16816(C[1][3], a1[cur], b1[cur] + 2);
    }
}
__device__ __forceinline__ void zeroC(float C[2][4][4]) {
    #pragma unroll
    for (int i = 0; i < 2; i++)
        #pragma unroll
        for (int j = 0; j < 4; j++)
            #pragma unroll
            for (int q = 0; q < 4; q++) C[i][j][q] = 0.f;
}
// cp.async one 64-dim x 128-ch fp16 weight slice into ROWB-strided smem (256 thr)
__device__ __forceinline__ void cpW64(uint32_t dstbase, const __half* __restrict__ src, int tid) {
    #pragma unroll
    for (int i = tid; i < 1024; i += 256) {
        uint32_t off = (i >> 4) * (ROWB * 2) + (i & 15) * 16;
        CP16(dstbase + off, (const char*)src + i * 16);
    }
}

// ---------------- P0: weights -> fp16 ----------------
__global__ __launch_bounds__(512) void attn_p0(
    const float* __restrict__ Wk, const float* __restrict__ Wv,
    const float* __restrict__ Wq)
{
    const float* src = (blockIdx.y == 0) ? Wk : (blockIdx.y == 1) ? Wv : Wq;
    const float4* W4 = (const float4*)src;
    int idx = blockIdx.x * 512 + threadIdx.x;       // grid.x = 32 -> 16384 float4
    float4 v = W4[idx];
    __half2 a = __floats2half2_rn(v.x, v.y), b = __floats2half2_rn(v.z, v.w);
    *(uint2*)(g_W16 + (size_t)blockIdx.y * 65536 + idx * 4) =
        make_uint2(*(uint32_t*)&a, *(uint32_t*)&b);
}

// ---------------- P1 (256 threads, 2 CTAs/SM, head-half split) ----------------
#define SMEM1 (34816 + 2 * 17408 + 17408 + 17408 + 6144 + 1024)

__global__ __launch_bounds__(256, 2) void attn_p1(
    const float* __restrict__ x,
    const float* __restrict__ bq, const float* __restrict__ bk,
    const float* __restrict__ bv)
{
    __half* xh  = (__half*)smraw;            // [128 tok][ROWB]
    __half* w0  = xh + 128 * ROWB;           // W slot 0 [64][ROWB]
    __half* w1  = w0 + 64 * ROWB;            // W slot 1
    __half* ekT = w1 + 64 * ROWB;            // [64 dim][ROWB tok]
    __half* vT  = ekT + 64 * ROWB;
    float* sb_bk = (float*)(vT + 64 * ROWB);
    float* sb_bv = sb_bk + 512;
    float* sb_bq = sb_bv + 512;
    float* sb_se = sb_bq + 512;              // [64 dim][4 tok-group]

    const uint32_t uxh = smem_u32(xh);
    const uint32_t uw0 = smem_u32(w0), uw1 = smem_u32(w1);
    const uint32_t uek = smem_u32(ekT), uvt = smem_u32(vT);

    const int tid = threadIdx.x, w = tid >> 5, lane = tid & 31;
    const int tile = blockIdx.x, b = blockIdx.y, hh = blockIdx.z;
    const int bt = b * 128 + tile;
    const float* xb = x + (size_t)b * 128 * 16384 + (size_t)tile * 128;

    const int hoff = hh * 64 * 128;

    cpW64(uw0, g_W16 + hoff, tid);           // Wk(0) slice -> slot 0
    CPCOMMIT();

    sb_bk[tid] = bk[tid];        sb_bk[tid + 256] = bk[tid + 256];
    sb_bv[tid] = bv[tid];        sb_bv[tid + 256] = bv[tid + 256];
    sb_bq[tid] = bq[tid];        sb_bq[tid + 256] = bq[tid + 256];

    // x tile -> fp16, layout [tok][ch]
    #pragma unroll
    for (int idx = tid; idx < 4096; idx += 256) {
        int c = idx >> 5, t = (idx & 31) << 2;
        float4 v = *(const float4*)(xb + (size_t)c * 16384 + t);
        xh[t * ROWB + c]       = __float2half_rn(v.x);
        xh[(t + 1) * ROWB + c] = __float2half_rn(v.y);
        xh[(t + 2) * ROWB + c] = __float2half_rn(v.z);
        xh[(t + 3) * ROWB + c] = __float2half_rn(v.w);
    }
    CPWAIT(0);
    __syncthreads();

    const int wm = (w >> 2) * 32;     // dim block within the 64-dim head slice
    const int wn = (w & 3) * 32;      // token block

    for (int p = 0; p < 4; p++) {
        const int gd = p * 128 + hh * 64;          // global dim base of this head
        const uint32_t usk = ((3 * p) & 1) ? uw1 : uw0;       // Wk slot
        const uint32_t usv = ((3 * p + 1) & 1) ? uw1 : uw0;   // Wv slot
        const uint32_t usq = ((3 * p + 2) & 1) ? uw1 : uw0;   // Wq slot
        const uint32_t unk = ((3 * p + 3) & 1) ? uw1 : uw0;   // next Wk slot

        float C[2][4][4];

        // ---- phase A: K proj, D[dim64][tok128] ----
        cpW64(usv, g_W16 + 65536 + p * 16384 + hoff, tid);    // Wv(p) slice
        CPCOMMIT();
        zeroC(C);
        gemm32x32(C, usk, uxh, wm, wn);
        {
            float se[4] = {0.f, 0.f, 0.f, 0.f};
            #pragma unroll
            for (int i = 0; i < 2; i++) {
                const int dim0 = wm + 16 * i + (lane >> 2);
                const float b0 = sb_bk[gd + dim0];
                const float b8 = sb_bk[gd + dim0 + 8];
                #pragma unroll
                for (int j = 0; j < 4; j++) {
                    const int tok = wn + 8 * j + ((lane & 3) << 1);
                    __half2 h01 = __floats2half2_rn(__expf(QSCALE * (C[i][j][0] + b0)),
                                                    __expf(QSCALE * (C[i][j][1] + b0)));
                    __half2 h23 = __floats2half2_rn(__expf(QSCALE * (C[i][j][2] + b8)),
                                                    __expf(QSCALE * (C[i][j][3] + b8)));
                    *(__half2*)(ekT + dim0 * ROWB + tok)       = h01;
                    *(__half2*)(ekT + (dim0 + 8) * ROWB + tok) = h23;
                    se[2 * i]     += __low2float(h01) + __high2float(h01);
                    se[2 * i + 1] += __low2float(h23) + __high2float(h23);
                }
            }
            #pragma unroll
            for (int q = 0; q < 4; q++) {
                se[q] += __shfl_xor_sync(0xffffffffu, se[q], 1);
                se[q] += __shfl_xor_sync(0xffffffffu, se[q], 2);
            }
            if ((lane & 3) == 0) {
                const int d0 = wm + (lane >> 2), g = w & 3;
                sb_se[d0 * 4 + g]        = se[0];
                sb_se[(d0 + 8) * 4 + g]  = se[1];
                sb_se[(d0 + 16) * 4 + g] = se[2];
                sb_se[(d0 + 24) * 4 + g] = se[3];
            }
        }
        CPWAIT(0);
        __syncthreads();

        // finalize per-dim ek sums -> transposed gmem
        if (tid < 64) {
            float4 v = *(const float4*)(sb_se + tid * 4);
            g_spart[(size_t)(gd + tid) * 512 + bt] = v.x + v.y + v.z + v.w;
        }

        // ---- phase B: V proj, D[dim64][tok128] ----
        cpW64(usq, g_W16 + 131072 + p * 16384 + hoff, tid);   // Wq(p) slice
        CPCOMMIT();
        zeroC(C);
        gemm32x32(C, usv, uxh, wm, wn);
        #pragma unroll
        for (int i = 0; i < 2; i++) {
            const int dim0 = wm + 16 * i + (lane >> 2);
            const float b0 = sb_bv[gd + dim0];
            const float b8 = sb_bv[gd + dim0 + 8];
            #pragma unroll
            for (int j = 0; j < 4; j++) {
                const int tok = wn + 8 * j + ((lane & 3) << 1);
                *(__half2*)(vT + dim0 * ROWB + tok) =
                    __floats2half2_rn(C[i][j][0] + b0, C[i][j][1] + b0);
                *(__half2*)(vT + (dim0 + 8) * ROWB + tok) =
                    __floats2half2_rn(C[i][j][2] + b8, C[i][j][3] + b8);
            }
        }
        CPWAIT(0);
        __syncthreads();

        // ---- phase C: ctx GEMM + Q proj (register softmax) ----
        if (p < 3) {
            cpW64(unk, g_W16 + (p + 1) * 16384 + hoff, tid);  // Wk(p+1) slice
            CPCOMMIT();
        }
        {   // ctx: D[d64][e64] = sum_t ekT[d][t] * vT[e][t]; warp = 16d x 32e
            const int r0 = (w >> 1) * 16;
            const int e0 = (w & 1) * 32;
            float Cc[4][4];
            #pragma unroll
            for (int j = 0; j < 4; j++)
                #pragma unroll
                for (int q = 0; q < 4; q++) Cc[j][q] = 0.f;
            #pragma unroll
            for (int k0 = 0; k0 < 128; k0 += 16) {
                uint32_t a[4], b0[4], b1[4];
                ldmx4(a, a_addr(uek, r0, k0));
                ldmx4(b0, b_addr(uvt, e0, k0));
                ldmx4(b1, b_addr(uvt, e0 + 16, k0));
                mma16816(Cc[0], a, b0 + 0);  mma16816(Cc[1], a, b0 + 2);
                mma16816(Cc[2], a, b1 + 0);  mma16816(Cc[3], a, b1 + 2);
            }
            float* dst = g_ctxp + ((size_t)bt * 8 + 2 * p + hh) * 4096;
            const int d0 = r0 + (lane >> 2);
            #pragma unroll
            for (int j = 0; j < 4; j++) {
                int e = e0 + 8 * j + ((lane & 3) << 1);
                *(float2*)(dst + d0 * 64 + e)       = make_float2(Cc[j][0], Cc[j][1]);
                *(float2*)(dst + (d0 + 8) * 64 + e) = make_float2(Cc[j][2], Cc[j][3]);
            }
        }
        {   // Q proj: warp = 16 tokens x full 64-dim head
            const int wqm = w * 16;            // token block (8 warps x 16 = 128)
            float Cq[8][4];
            #pragma unroll
            for (int j = 0; j < 8; j++)
                #pragma unroll
                for (int q = 0; q < 4; q++) Cq[j][q] = 0.f;
            #pragma unroll
            for (int k0 = 0; k0 < 128; k0 += 16) {
                uint32_t a[4], bb[4][4];
                ldmx4(a, a_addr(uxh, wqm, k0));
                #pragma unroll
                for (int jj = 0; jj < 4; jj++)
                    ldmx4(bb[jj], b_addr(usq, 16 * jj, k0));
                #pragma unroll
                for (int jj = 0; jj < 4; jj++) {
                    mma16816(Cq[2 * jj],     a, bb[jj] + 0);
                    mma16816(Cq[2 * jj + 1], a, bb[jj] + 2);
                }
            }
            __half2 hv0[8], hv1[8];
            float s0 = 0.f, s1 = 0.f;
            #pragma unroll
            for (int jf = 0; jf < 8; jf++) {
                int dim = 8 * jf + ((lane & 3) << 1);
                float b0 = sb_bq[gd + dim], b1 = sb_bq[gd + dim + 1];
                __half2 h01 = __floats2half2_rn(__expf(QSCALE * (Cq[jf][0] + b0)),
                                                __expf(QSCALE * (Cq[jf][1] + b1)));
                __half2 h23 = __floats2half2_rn(__expf(QSCALE * (Cq[jf][2] + b0)),
                                                __expf(QSCALE * (Cq[jf][3] + b1)));
                hv0[jf] = h01;  hv1[jf] = h23;
                s0 += __low2float(h01) + __high2float(h01);
                s1 += __low2float(h23) + __high2float(h23);
            }
            s0 += __shfl_xor_sync(0xffffffffu, s0, 1);
            s0 += __shfl_xor_sync(0xffffffffu, s0, 2);
            s1 += __shfl_xor_sync(0xffffffffu, s1, 1);
            s1 += __shfl_xor_sync(0xffffffffu, s1, 2);
            const float r0 = 1.f / s0, r1 = 1.f / s1;
            const int tok = wqm + (lane >> 2);
            __half* qdst = g_qs + ((size_t)bt * 4 + p) * 16384 + hh * 64;
            #pragma unroll
            for (int jf = 0; jf < 8; jf++) {
                int dim = 8 * jf + ((lane & 3) << 1);
                __half2 v0 = hv0[jf], v1 = hv1[jf];
                *(__half2*)(qdst + tok * 128 + dim) =
                    __floats2half2_rn(__low2float(v0) * r0, __high2float(v0) * r0);
                *(__half2*)(qdst + (tok + 8) * 128 + dim) =
                    __floats2half2_rn(__low2float(v1) * r1, __high2float(v1) * r1);
            }
        }
        CPWAIT(0);
        __syncthreads();   // protect ekT/vT/W slots before next chunk
    }
}

// ---------------- P2: fused reduce + normalize + fold Wo -> M ----------------
// grid (32 bh, 8 d-slices), 256 threads.
#define SMEM2 ((520 + 8 + 8192) * 4)

__global__ __launch_bounds__(256) void attn_p2(const float* __restrict__ Wo)
{
    float* ctx_s = (float*)smraw;      // [8][65] padded
    float* rS    = ctx_s + 520;        // [8]
    float* wo_s  = rS + 8;             // [128 o][64 e]
    const int bh = blockIdx.x, sl = blockIdx.y;
    const int b = bh >> 3, h = bh & 7;
    const int tid = threadIdx.x;

    for (int i = tid; i < 2048; i += 256) {
        int o = i >> 4, e4 = (i & 15) << 2;
        *(float4*)(wo_s + o * 64 + e4) = *(const float4*)(Wo + o * 512 + h * 64 + e4);
    }
    {
        const size_t base = (size_t)b * 128 * 32768 + (size_t)h * 4096 + sl * 512;
        const float* p0 = g_ctxp + base + tid;
        const float* p1 = p0 + 256;
        float s0 = 0.f, s1 = 0.f;
        #pragma unroll 8
        for (int t = 0; t < 128; t++) {
            s0 += p0[(size_t)t * 32768];
            s1 += p1[(size_t)t * 32768];
        }
        int i0 = tid, i1 = tid + 256;
        ctx_s[(i0 >> 6) * 65 + (i0 & 63)] = s0;
        ctx_s[(i1 >> 6) * 65 + (i1 & 63)] = s1;
    }
    if (tid < 32) {
        const int d8 = tid >> 2, part = tid & 3;
        const float4* src = (const float4*)(g_spart
            + (size_t)(h * 64 + sl * 8 + d8) * 512 + b * 128 + part * 32);
        float s = 0.f;
        #pragma unroll
        for (int i = 0; i < 8; i++) {
            float4 v = src[i];
            s += v.x + v.y + v.z + v.w;
        }
        s += __shfl_xor_sync(0xffffffffu, s, 1);
        s += __shfl_xor_sync(0xffffffffu, s, 2);
        if (part == 0) rS[d8] = 1.f / s;
    }
    __syncthreads();

    const size_t mb = (size_t)(b * 4 + (h >> 1)) * 16384 + (h & 1) * 64 + sl * 8;
    for (int i = tid; i < 1024; i += 256) {
        int o = i >> 3, d = i & 7;
        float s = 0.f;
        #pragma unroll 8
        for (int e = 0; e < 64; e++)
            s = fmaf(wo_s[o * 64 + e], ctx_s[d * 65 + e], s);
        g_Mh[mb + o * 128 + d] = __float2half_rn(s * rS[d]);
    }
}

// ---------------- P3 (256 threads, 2 CTAs/SM, token-half split) ----------------
// CTA = (tile, b, tok-half). Per chunk: M full (128o) + qn half (64 tok).
// smem: m0,m1 (2x34816) + q0,q1 (2x17408) + bo(512)
#define SMEM3 (2 * 128 * ROWB * 2 + 2 * 64 * ROWB * 2 + 512)

__global__ __launch_bounds__(256, 2) void attn_p3(
    const float* __restrict__ bo, float* __restrict__ out)
{
    __half* m0 = (__half*)smraw;
    __half* m1 = m0 + 128 * ROWB;
    __half* q0 = m1 + 128 * ROWB;
    __half* q1 = q0 + 64 * ROWB;
    float* sb_bo = (float*)(q1 + 64 * ROWB);

    const uint32_t um[2] = { smem_u32(m0), smem_u32(m1) };
    const uint32_t uq[2] = { smem_u32(q0), smem_u32(q1) };

    const int tid = threadIdx.x, w = tid >> 5, lane = tid & 31;
    const int tile = blockIdx.x, b = blockIdx.y, th = blockIdx.z;
    const int bt = b * 128 + tile;

    if (tid < 128) sb_bo[tid] = bo[tid];

    // prologue: chunk 0 -> slot 0
    {
        const char* msrc = (const char*)(g_Mh + (size_t)(b * 4) * 16384);
        const char* qsrc = (const char*)(g_qs + (size_t)(bt * 4) * 16384 + th * 64 * 128);
        #pragma unroll
        for (int i = tid; i < 2048; i += 256) {
            uint32_t off = (i >> 4) * (ROWB * 2) + (i & 15) * 16;
            CP16(um[0] + off, msrc + i * 16);
        }
        #pragma unroll
        for (int i = tid; i < 1024; i += 256) {
            uint32_t off = (i >> 4) * (ROWB * 2) + (i & 15) * 16;
            CP16(uq[0] + off, qsrc + i * 16);
        }
        CPCOMMIT();
    }

    const int wm = (w >> 1) * 32;   // o block (4)
    const int wn = (w & 1) * 32;    // token block within half (2)
    float Co[2][4][4];
    zeroC(Co);

    for (int p = 0; p < 4; p++) {
        const int cur = p & 1;
        if (p < 3) {
            const int nxt = cur ^ 1;
            const char* msrc = (const char*)(g_Mh + (size_t)(b * 4 + p + 1) * 16384);
            const char* qsrc = (const char*)(g_qs + (size_t)(bt * 4 + p + 1) * 16384
                                             + th * 64 * 128);
            #pragma unroll
            for (int i = tid; i < 2048; i += 256) {
                uint32_t off = (i >> 4) * (ROWB * 2) + (i & 15) * 16;
                CP16(um[nxt] + off, msrc + i * 16);
            }
            #pragma unroll
            for (int i = tid; i < 1024; i += 256) {
                uint32_t off = (i >> 4) * (ROWB * 2) + (i & 15) * 16;
                CP16(uq[nxt] + off, qsrc + i * 16);
            }
            CPCOMMIT();
            CPWAIT(1);
        } else {
            CPWAIT(0);
        }
        __syncthreads();
        gemm32x32(Co, um[cur], uq[cur], wm, wn);
        __syncthreads();
    }

    float* ob = out + (size_t)b * 128 * 16384 + (size_t)tile * 128 + th * 64;
    #pragma unroll
    for (int i = 0; i < 2; i++)
        #pragma unroll
        for (int j = 0; j < 4; j++) {
            int o = wm + 16 * i + (lane >> 2);
            int t = wn + 8 * j + ((lane & 3) << 1);
            float bo0 = sb_bo[o], bo8 = sb_bo[o + 8];
            *(float2*)(ob + (size_t)o * 16384 + t) =
                make_float2(Co[i][j][0] + bo0, Co[i][j][1] + bo0);
            *(float2*)(ob + (size_t)(o + 8) * 16384 + t) =
                make_float2(Co[i][j][2] + bo8, Co[i][j][3] + bo8);
        }
}

// ---------------------------------------------------------------------------
extern "C" void kernel_launch(void* const* d_in, const int* in_sizes, int n_in,
                              void* d_out, int out_size)
{
    const float* x  = (const float*)d_in[0];
    const float* Wq = (const float*)d_in[1];
    const float* bq = (const float*)d_in[2];
    const float* Wk = (const float*)d_in[3];
    const float* bk = (const float*)d_in[4];
    const float* Wv = (const float*)d_in[5];
    const float* bv = (const float*)d_in[6];
    const float* Wo = (const float*)d_in[7];
    const float* bo = (const float*)d_in[8];
    float* out = (float*)d_out;

    cudaFuncSetAttribute(attn_p1, cudaFuncAttributeMaxDynamicSharedMemorySize, SMEM1);
    cudaFuncSetAttribute(attn_p2, cudaFuncAttributeMaxDynamicSharedMemorySize, SMEM2);
    cudaFuncSetAttribute(attn_p3, cudaFuncAttributeMaxDynamicSharedMemorySize, SMEM3);

    attn_p0<<<dim3(32, 3), 512>>>(Wk, Wv, Wq);
    attn_p1<<<dim3(128, 4, 2), 256, SMEM1>>>(x, bq, bk, bv);
    attn_p2<<<dim3(32, 8), 256, SMEM2>>>(Wo);
    attn_p3<<<dim3(128, 4, 2), 256, SMEM3>>>(bo, out);
}